// round 9
// baseline (speedup 1.0000x reference)
#include <cuda_runtime.h>
#include <cstdint>

#define NN 100000
#define NE 1600000
#define D 128
#define EDIM 16
#define TILE_M 32
#define SCAN_BLK 1024
#define NSCAN ((NN + SCAN_BLK - 1) / SCAN_BLK)   // 98
#define HS_STRIDE 132   // multiple of 4 floats -> float4 stores stay 16B-aligned

// ---------------------------------------------------------------------------
// Scratch lives inside d_out's eh region (out + NN*D, 25.6M floats = 102MB).
// eh copy runs LAST and overwrites it.
// ---------------------------------------------------------------------------
#define AGG_OFF   0
#define ESRC_OFF  ((size_t)NN * D)
#define CNT_OFF   (ESRC_OFF + NE)
#define OFF_OFF   (CNT_OFF + NN)
#define CUR_OFF   (OFF_OFF + NN)
#define BSUM_OFF  (CUR_OFF + NN)
#define DIS_OFF   (BSUM_OFF + NSCAN)

// ---------------------------------------------------------------------------
// Packed f32x2 helpers (Blackwell FFMA2 — only reachable via PTX fma.rn.f32x2)
// ---------------------------------------------------------------------------
__device__ __forceinline__ unsigned long long pack2(float lo, float hi) {
    unsigned long long r;
    asm("mov.b64 %0, {%1, %2};" : "=l"(r) : "f"(lo), "f"(hi));
    return r;
}
__device__ __forceinline__ unsigned long long bcast2(float v) {
    unsigned long long r;
    asm("mov.b64 %0, {%1, %1};" : "=l"(r) : "f"(v));
    return r;
}
__device__ __forceinline__ void fma2(unsigned long long& d,
                                     unsigned long long a,
                                     unsigned long long b) {
    asm("fma.rn.f32x2 %0, %1, %2, %0;" : "+l"(d) : "l"(a), "l"(b));
}
__device__ __forceinline__ float2 unpack2(unsigned long long v) {
    float2 f;
    asm("mov.b64 {%0, %1}, %2;" : "=f"(f.x), "=f"(f.y) : "l"(v));
    return f;
}

// ---------------------------------------------------------------------------
__global__ void zero_cnt_kernel(int* __restrict__ cnt) {
    int i = blockIdx.x * blockDim.x + threadIdx.x;
    if (i < NN) cnt[i] = 0;
}

// ---------------------------------------------------------------------------
__global__ void count_kernel(const int* __restrict__ dst,
                             int* __restrict__ cnt) {
    int e = blockIdx.x * blockDim.x + threadIdx.x;
    if (e < NE) atomicAdd(&cnt[dst[e]], 1);
}

// ---------------------------------------------------------------------------
__global__ __launch_bounds__(SCAN_BLK) void scan1_kernel(
    const int* __restrict__ cnt, int* __restrict__ off, int* __restrict__ bsum)
{
    __shared__ int s[SCAN_BLK];
    int gid = blockIdx.x * SCAN_BLK + threadIdx.x;
    int v = (gid < NN) ? cnt[gid] : 0;
    s[threadIdx.x] = v;
    __syncthreads();
    #pragma unroll
    for (int o = 1; o < SCAN_BLK; o <<= 1) {
        int t = (threadIdx.x >= o) ? s[threadIdx.x - o] : 0;
        __syncthreads();
        s[threadIdx.x] += t;
        __syncthreads();
    }
    if (gid < NN) off[gid] = s[threadIdx.x] - v;   // exclusive
    if (threadIdx.x == SCAN_BLK - 1) bsum[blockIdx.x] = s[SCAN_BLK - 1];
}

// ---------------------------------------------------------------------------
// Parallel exclusive scan over NSCAN=98 block totals (1 block, 128 threads).
// ---------------------------------------------------------------------------
__global__ void scan2_kernel(int* __restrict__ bsum) {
    __shared__ int s[128];
    int tid = threadIdx.x;
    int v = (tid < NSCAN) ? bsum[tid] : 0;
    s[tid] = v;
    __syncthreads();
    #pragma unroll
    for (int o = 1; o < 128; o <<= 1) {
        int t = (tid >= o) ? s[tid - o] : 0;
        __syncthreads();
        s[tid] += t;
        __syncthreads();
    }
    if (tid < NSCAN) bsum[tid] = s[tid] - v;   // exclusive
}

// ---------------------------------------------------------------------------
__global__ void finalize_kernel(const int* __restrict__ cnt,
                                const int* __restrict__ bsum,
                                int* __restrict__ off, int* __restrict__ cur,
                                float* __restrict__ dis)
{
    int i = blockIdx.x * blockDim.x + threadIdx.x;
    if (i < NN) {
        int o = off[i] + bsum[i >> 10];
        off[i] = o;
        cur[i] = o;
        int c = cnt[i];
        dis[i] = (c > 0) ? rsqrtf((float)c) : 0.f;
    }
}

// ---------------------------------------------------------------------------
__global__ void bucket_kernel(const int* __restrict__ src,
                              const int* __restrict__ dst,
                              int* __restrict__ cur, int* __restrict__ esrc)
{
    int e = blockIdx.x * blockDim.x + threadIdx.x;
    if (e < NE) {
        int d = dst[e];
        int pos = atomicAdd(&cur[d], 1);
        esrc[pos] = src[e];
    }
}

// ---------------------------------------------------------------------------
// Aggregate: one warp per destination node, lane = one float4 of the row.
// agg[n] = dis[n] * sum_{e in CSR[n]} dis[src_e] * nh[src_e]
// ---------------------------------------------------------------------------
__global__ __launch_bounds__(256) void aggregate_kernel(
    const float* __restrict__ nh, const int* __restrict__ esrc,
    const int* __restrict__ off, const int* __restrict__ cnt,
    const float* __restrict__ dis, float* __restrict__ agg)
{
    int n = (blockIdx.x * blockDim.x + threadIdx.x) >> 5;
    int lane = threadIdx.x & 31;
    if (n >= NN) return;
    int beg = off[n];
    int c = cnt[n];
    const float4* nh4 = (const float4*)nh;
    float4 acc = make_float4(0.f, 0.f, 0.f, 0.f);
    #pragma unroll 4
    for (int i = 0; i < c; i++) {
        int s = esrc[beg + i];
        float sc = dis[s];
        float4 v = nh4[(size_t)s * (D / 4) + lane];
        acc.x += sc * v.x; acc.y += sc * v.y;
        acc.z += sc * v.z; acc.w += sc * v.w;
    }
    float dn = dis[n];
    acc.x *= dn; acc.y *= dn; acc.z *= dn; acc.w *= dn;
    ((float4*)agg)[(size_t)n * (D / 4) + lane] = acc;
}

// ---------------------------------------------------------------------------
// Fused 2-layer MLP with packed f32x2 FMA.
// As: input tile, stride 129 (scalar access only).
// Hs: hidden tile, stride 132 (multiple of 4 -> aligned float4 stores).
// ---------------------------------------------------------------------------
__global__ __launch_bounds__(128) void mlp_fused_kernel(
    const float* __restrict__ in,
    const float* __restrict__ W1, const float* __restrict__ b1,
    const float* __restrict__ W2, const float* __restrict__ b2,
    float* __restrict__ out)
{
    __shared__ float As[TILE_M * 129];
    __shared__ __align__(16) float Hs[TILE_M * HS_STRIDE];

    int tid = threadIdx.x;
    int m0 = blockIdx.x * TILE_M;
    int cg = tid & 31;
    int rg = tid >> 5;

    for (int idx = tid; idx < TILE_M * D; idx += 128) {
        int r = idx >> 7, c = idx & 127;
        As[r * 129 + c] = in[(size_t)(m0 + r) * D + c];
    }
    __syncthreads();

    unsigned long long acc2[8][2];

    // ---------------- Layer 1: h = relu(A @ W1 + b1) ----------------
    {
        float4 bias = ((const float4*)b1)[cg];
        unsigned long long bl = pack2(bias.x, bias.y);
        unsigned long long bh = pack2(bias.z, bias.w);
        #pragma unroll
        for (int m = 0; m < 8; m++) { acc2[m][0] = bl; acc2[m][1] = bh; }

        const float* Arow = As + rg * 8 * 129;
        const float4* Wv = (const float4*)W1;
        #pragma unroll 4
        for (int i = 0; i < D; i++) {
            float4 w = Wv[i * 32 + cg];
            unsigned long long w01 = pack2(w.x, w.y);
            unsigned long long w23 = pack2(w.z, w.w);
            #pragma unroll
            for (int m = 0; m < 8; m++) {
                unsigned long long a2 = bcast2(Arow[m * 129 + i]);
                fma2(acc2[m][0], a2, w01);
                fma2(acc2[m][1], a2, w23);
            }
        }

        float* Hrow = Hs + rg * 8 * HS_STRIDE;
        #pragma unroll
        for (int m = 0; m < 8; m++) {
            float2 lo = unpack2(acc2[m][0]);
            float2 hi = unpack2(acc2[m][1]);
            float4 r = make_float4(fmaxf(lo.x, 0.f), fmaxf(lo.y, 0.f),
                                   fmaxf(hi.x, 0.f), fmaxf(hi.y, 0.f));
            *(float4*)(Hrow + m * HS_STRIDE + 4 * cg) = r;   // 16B-aligned
        }
    }
    __syncthreads();

    // ---------------- Layer 2: out = h @ W2 + b2 ----------------
    {
        float4 bias = ((const float4*)b2)[cg];
        unsigned long long bl = pack2(bias.x, bias.y);
        unsigned long long bh = pack2(bias.z, bias.w);
        #pragma unroll
        for (int m = 0; m < 8; m++) { acc2[m][0] = bl; acc2[m][1] = bh; }

        const float* Hrow = Hs + rg * 8 * HS_STRIDE;
        const float4* Wv = (const float4*)W2;
        #pragma unroll 4
        for (int i = 0; i < D; i++) {
            float4 w = Wv[i * 32 + cg];
            unsigned long long w01 = pack2(w.x, w.y);
            unsigned long long w23 = pack2(w.z, w.w);
            #pragma unroll
            for (int m = 0; m < 8; m++) {
                unsigned long long a2 = bcast2(Hrow[m * HS_STRIDE + i]);
                fma2(acc2[m][0], a2, w01);
                fma2(acc2[m][1], a2, w23);
            }
        }

        #pragma unroll
        for (int m = 0; m < 8; m++) {
            float2 lo = unpack2(acc2[m][0]);
            float2 hi = unpack2(acc2[m][1]);
            float4 r = make_float4(lo.x, lo.y, hi.x, hi.y);
            ((float4*)(out + (size_t)(m0 + rg * 8 + m) * D))[cg] = r;
        }
    }
}

// ---------------------------------------------------------------------------
// eh passthrough — runs LAST, overwriting the scratch region with real data
// ---------------------------------------------------------------------------
__global__ void copy_eh_kernel(const float4* __restrict__ src,
                               float4* __restrict__ dst, int n4) {
    int i = blockIdx.x * blockDim.x + threadIdx.x;
    int stride = gridDim.x * blockDim.x;
    for (; i < n4; i += stride) dst[i] = src[i];
}

// ---------------------------------------------------------------------------
extern "C" void kernel_launch(void* const* d_in, const int* in_sizes, int n_in,
                              void* d_out, int out_size) {
    const float* nh = (const float*)d_in[0];
    const float* eh = (const float*)d_in[1];
    const int*   ei = (const int*)d_in[2];   // INT32 (JAX x64-disabled)
    const float* W1 = (const float*)d_in[3];
    const float* b1 = (const float*)d_in[4];
    const float* W2 = (const float*)d_in[5];
    const float* b2 = (const float*)d_in[6];
    float* out = (float*)d_out;

    const int* src = ei;        // row 0
    const int* dst = ei + NE;   // row 1

    float* E    = out + (size_t)NN * D;
    float* agg  = E + AGG_OFF;
    int*   esrc = (int*)(E + ESRC_OFF);
    int*   cnt  = (int*)(E + CNT_OFF);
    int*   off  = (int*)(E + OFF_OFF);
    int*   cur  = (int*)(E + CUR_OFF);
    int*   bsum = (int*)(E + BSUM_OFF);
    float* dis  = E + DIS_OFF;

    zero_cnt_kernel<<<(NN + 255) / 256, 256>>>(cnt);
    count_kernel<<<(NE + 255) / 256, 256>>>(dst, cnt);
    scan1_kernel<<<NSCAN, SCAN_BLK>>>(cnt, off, bsum);
    scan2_kernel<<<1, 128>>>(bsum);
    finalize_kernel<<<(NN + 255) / 256, 256>>>(cnt, bsum, off, cur, dis);
    bucket_kernel<<<(NE + 255) / 256, 256>>>(src, dst, cur, esrc);
    aggregate_kernel<<<(NN * 32 + 255) / 256, 256>>>(nh, esrc, off, cnt, dis, agg);
    mlp_fused_kernel<<<NN / TILE_M, 128>>>(agg, W1, b1, W2, b2, out);
    copy_eh_kernel<<<2048, 256>>>((const float4*)eh, (float4*)E, NE * EDIM / 4);
}